// round 1
// baseline (speedup 1.0000x reference)
#include <cuda_runtime.h>
#include <math.h>

#define BB 32
#define FF 4096
#define HH 32
#define DD 128
#define LL 8192
#define NSPLIT 16
#define CH (LL/NSPLIT)          /* 512 */
#define SCALE 0.08838834764831845f   /* 1/sqrt(128) */

/* ---------------- scratch (device globals; no allocation allowed) -------- */
__device__ float g_q[BB*HH*DD];          /* 131072 */
__device__ float g_k[BB*DD];
__device__ float g_v[BB*DD];
__device__ float g_attn[BB*HH*DD];
__device__ float g_pm[BB*NSPLIT*HH];
__device__ float g_psum[BB*NSPLIT*HH];
__device__ float g_po[BB*NSPLIT*HH*DD]; /* 8 MB */

/* ---------------- zero scratch + output (atomics accumulate into these) -- */
__global__ void zero_kernel(float* __restrict__ out) {
    int i = blockIdx.x * 256 + threadIdx.x;   /* grid covers exactly 131072 */
    g_q[i] = 0.f;
    out[i] = 0.f;
    if (i < BB*DD) { g_k[i] = 0.f; g_v[i] = 0.f; }
}

/* ---------------- C[32,N] += A[32,4096] * W[4096,N]  (split-K, atomics) --
 * grid = (N/128, 16), 256 threads. Block tile 32x128, Kt = 256.
 * Microtile 4m x 4n per thread: 2 x LDS.128 per 16 FFMA.                  */
__global__ __launch_bounds__(256) void sgemm32(
        const float* __restrict__ A, const float* __restrict__ W,
        float* __restrict__ C, int N) {
    __shared__ float As[32][36];    /* [k][m], pad 36 -> float4-aligned rows */
    __shared__ float Ws[32][132];   /* [k][n] */
    int n0 = blockIdx.x * 128;
    int k0 = blockIdx.y * 256;
    int t  = threadIdx.x;
    int mi = t >> 5;        /* 0..7  -> m = mi*4 */
    int ni = t & 31;        /* 0..31 -> n = ni*4 */
    float acc[4][4];
#pragma unroll
    for (int i = 0; i < 4; i++)
#pragma unroll
        for (int j = 0; j < 4; j++) acc[i][j] = 0.f;

    for (int kb = 0; kb < 256; kb += 32) {
        int kg = k0 + kb;
#pragma unroll
        for (int p = 0; p < 4; p++) {           /* A tile, stored transposed */
            int i = t + p * 256;
            As[i & 31][i >> 5] = A[(i >> 5) * FF + kg + (i & 31)];
        }
#pragma unroll
        for (int p = 0; p < 4; p++) {           /* W tile (float4) */
            int i  = t + p * 256;
            int kk = i >> 5, nq = i & 31;
            *(float4*)&Ws[kk][nq * 4] =
                *(const float4*)&W[(kg + kk) * N + n0 + nq * 4];
        }
        __syncthreads();
#pragma unroll
        for (int kk = 0; kk < 32; kk++) {
            float4 a = *(float4*)&As[kk][mi * 4];
            float4 w = *(float4*)&Ws[kk][ni * 4];
            acc[0][0] += a.x*w.x; acc[0][1] += a.x*w.y; acc[0][2] += a.x*w.z; acc[0][3] += a.x*w.w;
            acc[1][0] += a.y*w.x; acc[1][1] += a.y*w.y; acc[1][2] += a.y*w.z; acc[1][3] += a.y*w.w;
            acc[2][0] += a.z*w.x; acc[2][1] += a.z*w.y; acc[2][2] += a.z*w.z; acc[2][3] += a.z*w.w;
            acc[3][0] += a.w*w.x; acc[3][1] += a.w*w.y; acc[3][2] += a.w*w.z; acc[3][3] += a.w*w.w;
        }
        __syncthreads();
    }
#pragma unroll
    for (int i = 0; i < 4; i++)
#pragma unroll
        for (int j = 0; j < 4; j++)
            atomicAdd(&C[(mi * 4 + i) * N + n0 + ni * 4 + j], acc[i][j]);
}

/* ---------------- RoPE on g_q (32 heads) and g_k --------------------------
 * grid (B, 33), 64 threads. Mimics the f32 reference rounding: freq is the
 * correctly-rounded f32 value of 10000^(-i/64); angle computed in f32.     */
__global__ void rope_kernel(const int* __restrict__ ci) {
    int b = blockIdx.x, hq = blockIdx.y, i = threadIdx.x;   /* i < 64 */
    float pos  = (float)ci[b];
    float freq = (float)exp(-(double)i * 0.14391156831212787); /* ln(1e4)/64 */
    float ang  = pos * freq;
    float s, c;
    sincosf(ang, &s, &c);
    float* p = (hq < HH) ? (g_q + (b * HH + hq) * DD) : (g_k + b * DD);
    float x1 = p[i], x2 = p[i + 64];
    p[i]      = x1 * c - x2 * s;
    p[i + 64] = x2 * c + x1 * s;
}

/* ---------------- flash-decode attention, split over L ---------------------
 * grid (B, NSPLIT), 256 threads. All H=32 heads share each K/V tile (MQA).
 * Thread t: logits for head h=t>>3, l-cols lt4=(t&7)*4; owns o[h][dblk..+15].
 * Dynamic smem: qs[32][128] | ksT[32][132] | vsT[32][132] | ps[32][33].     */
__global__ __launch_bounds__(256) void attn_kernel(
        const float* __restrict__ Kc, const float* __restrict__ Vc,
        const int* __restrict__ ci) {
    extern __shared__ float sm[];
    float* qs  = sm;                 /* 4096 floats */
    float* ksT = sm + 4096;          /* 4224 */
    float* vsT = ksT + 4224;         /* 4224 */
    float* ps  = vsT + 4224;         /* 1056 */

    int b = blockIdx.x, sp = blockIdx.y;
    int idx = ci[b];
    int c0  = sp * CH;
    int t = threadIdx.x;
    int h    = t >> 3;
    int lt4  = (t & 7) * 4;
    int dblk = (t & 7) * 16;

#pragma unroll
    for (int p = 0; p < 16; p++) {               /* q (pre-scaled) -> smem */
        int i = t + p * 256;
        qs[i] = g_q[b * HH * DD + i] * SCALE;
    }
    float o[16];
#pragma unroll
    for (int j = 0; j < 16; j++) o[j] = 0.f;
    float m_r = -1e30f, s_r = 0.f;

    int ntiles = 0;
    if (c0 <= idx) {
        int nvalid = min(idx + 1 - c0, CH);
        ntiles = (nvalid + 31) >> 5;
    }
    __syncthreads();

    const float* Kb = Kc + (size_t)b * DD * LL;
    const float* Vb = Vc + (size_t)b * DD * LL;

    for (int it = 0; it < ntiles; it++) {
        int l0 = c0 + it * 32;
        /* load K,V tiles transposed to [l][d]; fold the decode-step cache
           update (one-hot scatter-add) in at l == idx */
#pragma unroll
        for (int p = 0; p < 16; p++) {
            int i = t + p * 256;
            int d = i >> 5, ll = i & 31;
            int gl = l0 + ll;
            float kv = Kb[d * LL + gl];
            float vv = Vb[d * LL + gl];
            if (gl == idx) { kv += g_k[b * DD + d]; vv += g_v[b * DD + d]; }
            ksT[ll * 132 + d] = kv;
            vsT[ll * 132 + d] = vv;
        }
        __syncthreads();

        /* logits: f[j] = q[h,:] . k[:, lt4+j] */
        float f[4] = {0.f, 0.f, 0.f, 0.f};
#pragma unroll
        for (int dq = 0; dq < 32; dq++) {
            float4 q4 = *(float4*)&qs[h * 128 + dq * 4];
#pragma unroll
            for (int j = 0; j < 4; j++) {
                float4 k4 = *(float4*)&ksT[(lt4 + j) * 132 + dq * 4];
                f[j] += q4.x * k4.x + q4.y * k4.y + q4.z * k4.z + q4.w * k4.w;
            }
        }
#pragma unroll
        for (int j = 0; j < 4; j++)
            if (l0 + lt4 + j > idx) f[j] = -1e30f;

        /* online softmax within the 8-thread group that shares head h */
        float tm = fmaxf(fmaxf(f[0], f[1]), fmaxf(f[2], f[3]));
        tm = fmaxf(tm, __shfl_xor_sync(0xffffffffu, tm, 1));
        tm = fmaxf(tm, __shfl_xor_sync(0xffffffffu, tm, 2));
        tm = fmaxf(tm, __shfl_xor_sync(0xffffffffu, tm, 4));
        float m_new = fmaxf(m_r, tm);
        float corr  = __expf(m_r - m_new);
        float p0 = __expf(f[0] - m_new), p1 = __expf(f[1] - m_new);
        float p2 = __expf(f[2] - m_new), p3 = __expf(f[3] - m_new);
        float lsum = p0 + p1 + p2 + p3;
        lsum += __shfl_xor_sync(0xffffffffu, lsum, 1);
        lsum += __shfl_xor_sync(0xffffffffu, lsum, 2);
        lsum += __shfl_xor_sync(0xffffffffu, lsum, 4);
        s_r = s_r * corr + lsum;
        m_r = m_new;
        ps[h * 33 + lt4 + 0] = p0;
        ps[h * 33 + lt4 + 1] = p1;
        ps[h * 33 + lt4 + 2] = p2;
        ps[h * 33 + lt4 + 3] = p3;
#pragma unroll
        for (int j = 0; j < 16; j++) o[j] *= corr;
        __syncwarp();     /* ps written+read within the same warp only */

        /* PV: o[d] += sum_l p[h][l] * v[l][d] */
#pragma unroll
        for (int lt = 0; lt < 32; lt++) {
            float pv = ps[h * 33 + lt];
#pragma unroll
            for (int i4 = 0; i4 < 4; i4++) {
                float4 v = *(float4*)&vsT[lt * 132 + dblk + i4 * 4];
                o[i4 * 4 + 0] += pv * v.x;
                o[i4 * 4 + 1] += pv * v.y;
                o[i4 * 4 + 2] += pv * v.z;
                o[i4 * 4 + 3] += pv * v.w;
            }
        }
        __syncthreads();   /* protect ksT/vsT/ps for next tile */
    }

    /* write split partials (un-normalized) */
    int pb = (b * NSPLIT + sp) * HH + h;
    if ((t & 7) == 0) { g_pm[pb] = m_r; g_psum[pb] = s_r; }
    float* po = g_po + (size_t)pb * DD + dblk;
#pragma unroll
    for (int j = 0; j < 16; j += 4)
        *(float4*)&po[j] = make_float4(o[j], o[j+1], o[j+2], o[j+3]);
}

/* ---------------- combine split partials -> g_attn[b][h][d] -------------- */
__global__ void combine_kernel() {
    int bh = blockIdx.x;            /* 0..1023 */
    int b = bh >> 5, h = bh & 31;
    int d = threadIdx.x;            /* 0..127 */
    float m = -1e30f;
#pragma unroll
    for (int s = 0; s < NSPLIT; s++)
        m = fmaxf(m, g_pm[(b * NSPLIT + s) * HH + h]);
    float S = 0.f, acc = 0.f;
#pragma unroll
    for (int s = 0; s < NSPLIT; s++) {
        int ib = (b * NSPLIT + s) * HH + h;
        float w = __expf(g_pm[ib] - m);
        S   += w * g_psum[ib];
        acc += w * g_po[(size_t)ib * DD + d];
    }
    g_attn[(b * HH + h) * DD + d] = acc / S;
}

/* ---------------- launch ------------------------------------------------- */
extern "C" void kernel_launch(void* const* d_in, const int* in_sizes, int n_in,
                              void* d_out, int out_size) {
    const float* x  = (const float*)d_in[0];
    const float* Kc = (const float*)d_in[1];
    const float* Vc = (const float*)d_in[2];
    const float* Wq = (const float*)d_in[3];
    const float* Wk = (const float*)d_in[4];
    const float* Wv = (const float*)d_in[5];
    const float* Wo = (const float*)d_in[6];
    const int*   ci = (const int*)d_in[7];
    float* out = (float*)d_out;

    float *qp, *kp, *vp, *ap;
    cudaGetSymbolAddress((void**)&qp, g_q);
    cudaGetSymbolAddress((void**)&kp, g_k);
    cudaGetSymbolAddress((void**)&vp, g_v);
    cudaGetSymbolAddress((void**)&ap, g_attn);

    cudaFuncSetAttribute(attn_kernel,
                         cudaFuncAttributeMaxDynamicSharedMemorySize, 56000);

    zero_kernel<<<512, 256>>>(out);
    sgemm32<<<dim3(32, 16), 256>>>(x, Wq, qp, 4096);   /* q proj  */
    sgemm32<<<dim3(1, 16),  256>>>(x, Wk, kp, 128);    /* k proj  */
    sgemm32<<<dim3(1, 16),  256>>>(x, Wv, vp, 128);    /* v proj  */
    rope_kernel<<<dim3(32, 33), 64>>>(ci);
    attn_kernel<<<dim3(32, NSPLIT), 256, 54400>>>(Kc, Vc, ci);
    combine_kernel<<<1024, 128>>>();
    sgemm32<<<dim3(32, 16), 256>>>(ap, Wo, out, 4096); /* out proj */
}

// round 2
// speedup vs baseline: 3.6465x; 3.6465x over previous
#include <cuda_runtime.h>
#include <math.h>
#include <stdint.h>

#define BB 32
#define FF 4096
#define HH 32
#define DD 128
#define LL 8192
#define NSPLIT 16
#define CH (LL/NSPLIT)          /* 512 */
#define TL 128                  /* attention l-tile */
#define SCALE 0.08838834764831845f   /* 1/sqrt(128) */

/* ---------------- scratch (device globals; no allocation allowed) -------- */
__device__ float g_q[BB*HH*DD];
__device__ float g_k[BB*DD];
__device__ float g_v[BB*DD];
__device__ float g_attn[BB*HH*DD];
__device__ float g_pm[BB*NSPLIT*HH];
__device__ float g_psum[BB*NSPLIT*HH];
__device__ float g_po[BB*NSPLIT*HH*DD];

/* ---------------- cp.async helpers -------------------------------------- */
__device__ __forceinline__ uint32_t s2u(const void* p) {
    return (uint32_t)__cvta_generic_to_shared(p);
}
__device__ __forceinline__ void cpa16(uint32_t s, const void* g) {
    asm volatile("cp.async.cg.shared.global [%0], [%1], 16;" :: "r"(s), "l"(g));
}
__device__ __forceinline__ void cpcommit() {
    asm volatile("cp.async.commit_group;");
}
__device__ __forceinline__ void cpwait0() {
    asm volatile("cp.async.wait_group 0;");
}

/* ---------------- zero scratch + output --------------------------------- */
__global__ void zero_kernel(float* __restrict__ out) {
    int i = blockIdx.x * 256 + threadIdx.x;   /* 131072 */
    g_q[i] = 0.f;
    out[i] = 0.f;
    if (i < BB*DD) { g_k[i] = 0.f; g_v[i] = 0.f; }
}

/* ---------------- C[32,N] += A[32,4096]*W[4096,N], split-K, cp.async ----
 * grid (N/128, 16), 256 thr. A slice [32x256] loaded once; W double-buffered.
 * smem: As 256x36 floats | Ws 2 x 32x128 floats  = 69632 B                */
__global__ __launch_bounds__(256) void sgemm32(
        const float* __restrict__ A, const float* __restrict__ W,
        float* __restrict__ C, int N) {
    extern __shared__ float sm[];
    float* As = sm;                 /* 9216 floats */
    float* Ws = sm + 9216;          /* 8192 floats */
    const float4* As4 = (const float4*)As;
    const float4* Ws4 = (const float4*)Ws;
    uint32_t ws_u = s2u(Ws);

    int n0 = blockIdx.x * 128;
    int k0 = blockIdx.y * 256;
    int t  = threadIdx.x;
    int mi = t >> 5;        /* 0..7 */
    int ni = t & 31;        /* 0..31 */

    /* A slice -> As[k][m] (coalesced global, 4-way-conflict STS, one-time) */
#pragma unroll
    for (int p = 0; p < 32; p++) {
        int i = t + p * 256;
        int m = i >> 8, k = i & 255;
        As[k * 36 + m] = A[m * FF + k0 + k];
    }
    /* prologue: W tile 0 */
    {
#pragma unroll
        for (int p = 0; p < 4; p++) {
            int c = t + p * 256;
            int kk = c >> 5, nu = c & 31;
            cpa16(ws_u + (uint32_t)(kk * 128 + 4 * nu) * 4,
                  W + (size_t)(k0 + kk) * N + n0 + 4 * nu);
        }
        cpcommit();
    }

    float acc[4][4];
#pragma unroll
    for (int i = 0; i < 4; i++)
#pragma unroll
        for (int j = 0; j < 4; j++) acc[i][j] = 0.f;

    for (int kb = 0; kb < 8; kb++) {
        cpwait0();
        __syncthreads();
        int cur = kb & 1;
        if (kb < 7) {
            int nxt = cur ^ 1;
#pragma unroll
            for (int p = 0; p < 4; p++) {
                int c = t + p * 256;
                int kk = c >> 5, nu = c & 31;
                cpa16(ws_u + (uint32_t)(nxt * 4096 + kk * 128 + 4 * nu) * 4,
                      W + (size_t)(k0 + (kb + 1) * 32 + kk) * N + n0 + 4 * nu);
            }
            cpcommit();
        }
#pragma unroll
        for (int kk = 0; kk < 32; kk++) {
            float4 a = As4[(kb * 32 + kk) * 9 + mi];
            float4 w = Ws4[cur * 1024 + kk * 32 + ni];
            acc[0][0] += a.x*w.x; acc[0][1] += a.x*w.y; acc[0][2] += a.x*w.z; acc[0][3] += a.x*w.w;
            acc[1][0] += a.y*w.x; acc[1][1] += a.y*w.y; acc[1][2] += a.y*w.z; acc[1][3] += a.y*w.w;
            acc[2][0] += a.z*w.x; acc[2][1] += a.z*w.y; acc[2][2] += a.z*w.z; acc[2][3] += a.z*w.w;
            acc[3][0] += a.w*w.x; acc[3][1] += a.w*w.y; acc[3][2] += a.w*w.z; acc[3][3] += a.w*w.w;
        }
        __syncthreads();
    }
#pragma unroll
    for (int i = 0; i < 4; i++)
#pragma unroll
        for (int j = 0; j < 4; j++)
            atomicAdd(&C[(mi * 4 + i) * N + n0 + ni * 4 + j], acc[i][j]);
}

/* ---------------- RoPE on g_q and g_k ------------------------------------ */
__global__ void rope_kernel(const int* __restrict__ ci) {
    int b = blockIdx.x, hq = blockIdx.y, i = threadIdx.x;   /* i < 64 */
    float pos  = (float)ci[b];
    float freq = (float)exp(-(double)i * 0.14391156831212787);
    float ang  = pos * freq;
    float s, c;
    sincosf(ang, &s, &c);
    float* p = (hq < HH) ? (g_q + (b * HH + hq) * DD) : (g_k + b * DD);
    float x1 = p[i], x2 = p[i + 64];
    p[i]      = x1 * c - x2 * s;
    p[i + 64] = x2 * c + x1 * s;
}

/* ---------------- flash-decode attention ----------------------------------
 * grid (B, NSPLIT), 256 thr. warp w: heads 4w..4w+3.
 * QK: lane -> l = 4*lane (+lj).  PV: lane -> d = 4*lane (+di).
 * smem: qs[d][h] 128x36 | ks[d][l] 128x128 | vs[l][d] swizzled 128x128 |
 *       ps[h][l] 32x128  -> 165888 B                                      */
__global__ __launch_bounds__(256) void attn_kernel(
        const float* __restrict__ Kc, const float* __restrict__ Vc,
        const int* __restrict__ ci) {
    extern __shared__ float sm[];
    float* qs = sm;                 /* 4608 */
    float* ks = sm + 4608;          /* 16384 */
    float* vs = ks + 16384;         /* 16384 */
    float* ps = vs + 16384;         /* 4096  */
    const float4* qs4 = (const float4*)qs;
    const float4* ks4 = (const float4*)ks;
    float4* vs4 = (float4*)vs;
    float4* ps4 = (float4*)ps;
    uint32_t ks_u = s2u(ks);

    int b = blockIdx.x, sp = blockIdx.y;
    int idx = ci[b];
    int c0  = sp * CH;
    int t = threadIdx.x, w = t >> 5, lane = t & 31;

    int ntiles = 0;
    if (c0 <= idx) ntiles = (min(idx + 1 - c0, CH) + TL - 1) >> 7;

    const float* Kb = Kc + (size_t)b * DD * LL;
    const float* Vb = Vc + (size_t)b * DD * LL;

    /* prologue: K tile 0 via cp.async */
    if (ntiles > 0) {
#pragma unroll
        for (int p = 0; p < 16; p++) {
            int c = t + p * 256;
            int d = c >> 5, u = c & 31;
            cpa16(ks_u + (uint32_t)(d * 512 + u * 16),
                  Kb + (size_t)d * LL + c0 + 4 * u);
        }
        cpcommit();
    }

    /* q -> qs[d][h], pre-scaled */
#pragma unroll
    for (int p = 0; p < 16; p++) {
        int i = t + p * 256;
        int h = i >> 7, d = i & 127;
        qs[d * 36 + h] = g_q[b * HH * DD + i] * SCALE;
    }

    float4 o0 = {0,0,0,0}, o1 = {0,0,0,0}, o2 = {0,0,0,0}, o3 = {0,0,0,0};
    float m_r[4] = {-1e30f,-1e30f,-1e30f,-1e30f};
    float s_r[4] = {0,0,0,0};

    __syncthreads();

    for (int it = 0; it < ntiles; it++) {
        int l0 = c0 + it * TL;
        int hot = (l0 <= idx) && (idx < l0 + TL);

        /* V tile -> registers early (DRAM latency hides under QK) */
        float4 vr[16];
#pragma unroll
        for (int s = 0; s < 4; s++) {
            int dB = w + 8 * s;
#pragma unroll
            for (int j = 0; j < 4; j++)
                vr[s * 4 + j] = *(const float4*)&Vb[(size_t)(4 * dB + j) * LL + l0 + 4 * lane];
        }

        cpwait0();
        __syncthreads();
        if (hot) {
            if (t < 128) ks[t * 128 + (idx - l0)] += g_k[b * DD + t];
            __syncthreads();
        }

        /* QK: f[hj].{x..w} = logits for (head 4w+hj, l = 4*lane + lj) */
        float4 f0 = {0,0,0,0}, f1 = {0,0,0,0}, f2 = {0,0,0,0}, f3 = {0,0,0,0};
#pragma unroll 4
        for (int d = 0; d < 128; d++) {
            float4 q4 = qs4[d * 9 + w];
            float4 k4 = ks4[d * 32 + lane];
            f0.x += q4.x*k4.x; f0.y += q4.x*k4.y; f0.z += q4.x*k4.z; f0.w += q4.x*k4.w;
            f1.x += q4.y*k4.x; f1.y += q4.y*k4.y; f1.z += q4.y*k4.z; f1.w += q4.y*k4.w;
            f2.x += q4.z*k4.x; f2.y += q4.z*k4.y; f2.z += q4.z*k4.z; f2.w += q4.z*k4.w;
            f3.x += q4.w*k4.x; f3.y += q4.w*k4.y; f3.z += q4.w*k4.z; f3.w += q4.w*k4.w;
        }
        __syncthreads();               /* done reading ks */

        /* prefetch next K tile while we do softmax + PV */
        if (it + 1 < ntiles) {
            int l0n = l0 + TL;
#pragma unroll
            for (int p = 0; p < 16; p++) {
                int c = t + p * 256;
                int d = c >> 5, u = c & 31;
                cpa16(ks_u + (uint32_t)(d * 512 + u * 16),
                      Kb + (size_t)d * LL + l0n + 4 * u);
            }
            cpcommit();
        }

        /* causal mask (boundary tile only) */
        if (l0 + TL - 1 > idx) {
            int lb = l0 + 4 * lane;
            if (lb + 0 > idx) { f0.x = -1e30f; f1.x = -1e30f; f2.x = -1e30f; f3.x = -1e30f; }
            if (lb + 1 > idx) { f0.y = -1e30f; f1.y = -1e30f; f2.y = -1e30f; f3.y = -1e30f; }
            if (lb + 2 > idx) { f0.z = -1e30f; f1.z = -1e30f; f2.z = -1e30f; f3.z = -1e30f; }
            if (lb + 3 > idx) { f0.w = -1e30f; f1.w = -1e30f; f2.w = -1e30f; f3.w = -1e30f; }
        }

        /* online softmax per head (warp-wide over 128 l) */
        float corr[4];
#pragma unroll
        for (int hj = 0; hj < 4; hj++) {
            float4 f = (hj == 0) ? f0 : (hj == 1) ? f1 : (hj == 2) ? f2 : f3;
            float tm = fmaxf(fmaxf(f.x, f.y), fmaxf(f.z, f.w));
            tm = fmaxf(tm, __shfl_xor_sync(0xffffffffu, tm, 16));
            tm = fmaxf(tm, __shfl_xor_sync(0xffffffffu, tm, 8));
            tm = fmaxf(tm, __shfl_xor_sync(0xffffffffu, tm, 4));
            tm = fmaxf(tm, __shfl_xor_sync(0xffffffffu, tm, 2));
            tm = fmaxf(tm, __shfl_xor_sync(0xffffffffu, tm, 1));
            float mn = fmaxf(m_r[hj], tm);
            corr[hj] = __expf(m_r[hj] - mn);
            float p0 = __expf(f.x - mn), p1 = __expf(f.y - mn);
            float p2 = __expf(f.z - mn), p3 = __expf(f.w - mn);
            float ls = p0 + p1 + p2 + p3;
            ls += __shfl_xor_sync(0xffffffffu, ls, 16);
            ls += __shfl_xor_sync(0xffffffffu, ls, 8);
            ls += __shfl_xor_sync(0xffffffffu, ls, 4);
            ls += __shfl_xor_sync(0xffffffffu, ls, 2);
            ls += __shfl_xor_sync(0xffffffffu, ls, 1);
            s_r[hj] = s_r[hj] * corr[hj] + ls;
            m_r[hj] = mn;
            ps4[(4 * w + hj) * 32 + lane] = make_float4(p0, p1, p2, p3);
        }
        o0.x *= corr[0]; o0.y *= corr[0]; o0.z *= corr[0]; o0.w *= corr[0];
        o1.x *= corr[1]; o1.y *= corr[1]; o1.z *= corr[1]; o1.w *= corr[1];
        o2.x *= corr[2]; o2.y *= corr[2]; o2.z *= corr[2]; o2.w *= corr[2];
        o3.x *= corr[3]; o3.y *= corr[3]; o3.z *= corr[3]; o3.w *= corr[3];

        /* V regs -> vs[l][d] (register transpose, swizzled, conflict-free) */
#pragma unroll
        for (int s = 0; s < 4; s++) {
            int dB = w + 8 * s;
            int un = dB ^ (lane & 7);
            float4 a = vr[s*4+0], bb = vr[s*4+1], cc = vr[s*4+2], dd = vr[s*4+3];
            vs4[(4*lane + 0) * 32 + un] = make_float4(a.x, bb.x, cc.x, dd.x);
            vs4[(4*lane + 1) * 32 + un] = make_float4(a.y, bb.y, cc.y, dd.y);
            vs4[(4*lane + 2) * 32 + un] = make_float4(a.z, bb.z, cc.z, dd.z);
            vs4[(4*lane + 3) * 32 + un] = make_float4(a.w, bb.w, cc.w, dd.w);
        }
        __syncthreads();
        if (hot) {
            if (t < 128) {
                int li = idx - l0;
                int sw = (li >> 2) & 7;
                vs[li * 128 + (((t >> 2) ^ sw) << 2) + (t & 3)] += g_v[b * DD + t];
            }
            __syncthreads();
        }

        /* PV: o[hj].{x..w} += sum_l p[hj][l] * v[l][4*lane + di] */
#pragma unroll 2
        for (int lt = 0; lt < 128; lt += 4) {
            int swl = (lt >> 2) & 7;
            int vu = lane ^ swl;
            float4 v0 = vs4[(lt + 0) * 32 + vu];
            float4 v1 = vs4[(lt + 1) * 32 + vu];
            float4 v2 = vs4[(lt + 2) * 32 + vu];
            float4 v3 = vs4[(lt + 3) * 32 + vu];
            float4 pA = ps4[(4 * w + 0) * 32 + (lt >> 2)];
            float4 pB = ps4[(4 * w + 1) * 32 + (lt >> 2)];
            float4 pC = ps4[(4 * w + 2) * 32 + (lt >> 2)];
            float4 pD = ps4[(4 * w + 3) * 32 + (lt >> 2)];
            o0.x += pA.x*v0.x + pA.y*v1.x + pA.z*v2.x + pA.w*v3.x;
            o0.y += pA.x*v0.y + pA.y*v1.y + pA.z*v2.y + pA.w*v3.y;
            o0.z += pA.x*v0.z + pA.y*v1.z + pA.z*v2.z + pA.w*v3.z;
            o0.w += pA.x*v0.w + pA.y*v1.w + pA.z*v2.w + pA.w*v3.w;
            o1.x += pB.x*v0.x + pB.y*v1.x + pB.z*v2.x + pB.w*v3.x;
            o1.y += pB.x*v0.y + pB.y*v1.y + pB.z*v2.y + pB.w*v3.y;
            o1.z += pB.x*v0.z + pB.y*v1.z + pB.z*v2.z + pB.w*v3.z;
            o1.w += pB.x*v0.w + pB.y*v1.w + pB.z*v2.w + pB.w*v3.w;
            o2.x += pC.x*v0.x + pC.y*v1.x + pC.z*v2.x + pC.w*v3.x;
            o2.y += pC.x*v0.y + pC.y*v1.y + pC.z*v2.y + pC.w*v3.y;
            o2.z += pC.x*v0.z + pC.y*v1.z + pC.z*v2.z + pC.w*v3.z;
            o2.w += pC.x*v0.w + pC.y*v1.w + pC.z*v2.w + pC.w*v3.w;
            o3.x += pD.x*v0.x + pD.y*v1.x + pD.z*v2.x + pD.w*v3.x;
            o3.y += pD.x*v0.y + pD.y*v1.y + pD.z*v2.y + pD.w*v3.y;
            o3.z += pD.x*v0.z + pD.y*v1.z + pD.z*v2.z + pD.w*v3.z;
            o3.w += pD.x*v0.w + pD.y*v1.w + pD.z*v2.w + pD.w*v3.w;
        }
        __syncthreads();    /* vs/ps free for next tile */
    }

    /* split partials */
    int pb = (b * NSPLIT + sp) * HH;
    if (lane == 0) {
#pragma unroll
        for (int hj = 0; hj < 4; hj++) {
            g_pm[pb + 4 * w + hj]   = m_r[hj];
            g_psum[pb + 4 * w + hj] = s_r[hj];
        }
    }
    *(float4*)&g_po[((size_t)pb + 4 * w + 0) * DD + 4 * lane] = o0;
    *(float4*)&g_po[((size_t)pb + 4 * w + 1) * DD + 4 * lane] = o1;
    *(float4*)&g_po[((size_t)pb + 4 * w + 2) * DD + 4 * lane] = o2;
    *(float4*)&g_po[((size_t)pb + 4 * w + 3) * DD + 4 * lane] = o3;
}

/* ---------------- combine split partials -> g_attn ----------------------- */
__global__ void combine_kernel() {
    int bh = blockIdx.x;
    int b = bh >> 5, h = bh & 31;
    int d = threadIdx.x;
    float m = -1e30f;
#pragma unroll
    for (int s = 0; s < NSPLIT; s++)
        m = fmaxf(m, g_pm[(b * NSPLIT + s) * HH + h]);
    float S = 0.f, acc = 0.f;
#pragma unroll
    for (int s = 0; s < NSPLIT; s++) {
        int ib = (b * NSPLIT + s) * HH + h;
        float w = __expf(g_pm[ib] - m);
        S   += w * g_psum[ib];
        acc += w * g_po[(size_t)ib * DD + d];
    }
    g_attn[(b * HH + h) * DD + d] = acc / S;
}

/* ---------------- launch ------------------------------------------------- */
extern "C" void kernel_launch(void* const* d_in, const int* in_sizes, int n_in,
                              void* d_out, int out_size) {
    const float* x  = (const float*)d_in[0];
    const float* Kc = (const float*)d_in[1];
    const float* Vc = (const float*)d_in[2];
    const float* Wq = (const float*)d_in[3];
    const float* Wk = (const float*)d_in[4];
    const float* Wv = (const float*)d_in[5];
    const float* Wo = (const float*)d_in[6];
    const int*   ci = (const int*)d_in[7];
    float* out = (float*)d_out;

    float *qp, *kp, *vp, *ap;
    cudaGetSymbolAddress((void**)&qp, g_q);
    cudaGetSymbolAddress((void**)&kp, g_k);
    cudaGetSymbolAddress((void**)&vp, g_v);
    cudaGetSymbolAddress((void**)&ap, g_attn);

    cudaFuncSetAttribute(sgemm32,
                         cudaFuncAttributeMaxDynamicSharedMemorySize, 69632);
    cudaFuncSetAttribute(attn_kernel,
                         cudaFuncAttributeMaxDynamicSharedMemorySize, 165888);

    zero_kernel<<<512, 256>>>(out);
    sgemm32<<<dim3(32, 16), 256, 69632>>>(x, Wq, qp, 4096);
    sgemm32<<<dim3(1, 16),  256, 69632>>>(x, Wk, kp, 128);
    sgemm32<<<dim3(1, 16),  256, 69632>>>(x, Wv, vp, 128);
    rope_kernel<<<dim3(32, 33), 64>>>(ci);
    attn_kernel<<<dim3(32, NSPLIT), 256, 165888>>>(Kc, Vc, ci);
    combine_kernel<<<1024, 128>>>();
    sgemm32<<<dim3(32, 16), 256, 69632>>>(ap, Wo, out, 4096);
}

// round 3
// speedup vs baseline: 4.0045x; 1.0982x over previous
#include <cuda_runtime.h>
#include <math.h>
#include <stdint.h>

#define BB 32
#define FF 4096
#define HH 32
#define DD 128
#define LL 8192
#define NSPLIT 16
#define CH (LL/NSPLIT)
#define TL 128
#define SCALE 0.08838834764831845f

/* ---------------- scratch ------------------------------------------------ */
__device__ float g_q[BB*HH*DD];
__device__ float g_k[BB*DD];
__device__ float g_v[BB*DD];
__device__ float g_attn[BB*HH*DD];
__device__ float g_pm[BB*NSPLIT*HH];
__device__ float g_psum[BB*NSPLIT*HH];
__device__ float g_po[BB*NSPLIT*HH*DD];

/* ---------------- helpers ------------------------------------------------ */
__device__ __forceinline__ uint32_t s2u(const void* p) {
    return (uint32_t)__cvta_generic_to_shared(p);
}
__device__ __forceinline__ void cpa16(uint32_t s, const void* g) {
    asm volatile("cp.async.cg.shared.global [%0], [%1], 16;" :: "r"(s), "l"(g));
}
__device__ __forceinline__ void cpcommit() { asm volatile("cp.async.commit_group;"); }
__device__ __forceinline__ void cpwait0()  { asm volatile("cp.async.wait_group 0;"); }

__device__ __forceinline__ uint32_t f2tf(float x) {
    uint32_t r; asm("cvt.rna.tf32.f32 %0, %1;" : "=r"(r) : "f"(x)); return r;
}
__device__ __forceinline__ void mma8(float* d, const uint32_t* a, const uint32_t* b) {
    asm volatile("mma.sync.aligned.m16n8k8.row.col.f32.tf32.tf32.f32 "
        "{%0,%1,%2,%3},{%4,%5,%6,%7},{%8,%9},{%0,%1,%2,%3};"
        : "+f"(d[0]), "+f"(d[1]), "+f"(d[2]), "+f"(d[3])
        : "r"(a[0]), "r"(a[1]), "r"(a[2]), "r"(a[3]), "r"(b[0]), "r"(b[1]));
}

/* ---------------- zero --------------------------------------------------- */
__global__ void zero_kernel(float* __restrict__ out) {
    int i = blockIdx.x * 256 + threadIdx.x;
    g_q[i] = 0.f;
    out[i] = 0.f;
    if (i < BB*DD) { g_k[i] = 0.f; g_v[i] = 0.f; }
}

/* ---------------- tensor GEMM: C[32,N] += A[32,4096] * W[4096,N] ---------
 * 3xTF32 split precision. grid (N/256, 8). 256 thr = 8 warps, warp N=32.
 * smem: As[512][33] fp32 | Ws[2][32][264] fp32  (135168 B)                */
#define SPLITK 8
#define KSL (FF/SPLITK)   /* 512 */
__global__ __launch_bounds__(256) void tgemm32(
        const float* __restrict__ A, const float* __restrict__ W,
        float* __restrict__ C, int N) {
    extern __shared__ float sm[];
    float* As = sm;                 /* 16896 floats */
    float* Ws = sm + 16896;         /* 16896 floats */
    uint32_t ws_u = s2u(Ws);

    int n0 = blockIdx.x * 256;
    int k0 = blockIdx.y * KSL;
    int t = threadIdx.x, wp = t >> 5, lane = t & 31;
    int g = lane >> 2, c = lane & 3;

    /* A slice -> As[k][m], one-time */
#pragma unroll
    for (int p = 0; p < 64; p++) {
        int i = t + p * 256;
        int m = i >> 9, k = i & 511;
        As[k * 33 + m] = A[m * FF + k0 + k];
    }

    /* W tile prefetch (kb granularity 32 rows x 256 cols) */
    auto loadW = [&](int kb, int buf) {
        const float* src = W + (size_t)(k0 + kb * 32) * N + n0;
#pragma unroll
        for (int p = 0; p < 8; p++) {
            int ci = t + p * 256;
            int kk = ci >> 6, u = ci & 63;
            cpa16(ws_u + (uint32_t)((buf * 32 + kk) * 264 + 4 * u) * 4,
                  src + (size_t)kk * N + 4 * u);
        }
        cpcommit();
    };
    loadW(0, 0);

    float acc[2][4][4];
#pragma unroll
    for (int mt = 0; mt < 2; mt++)
#pragma unroll
        for (int nt = 0; nt < 4; nt++)
#pragma unroll
            for (int r = 0; r < 4; r++) acc[mt][nt][r] = 0.f;

    for (int kb = 0; kb < 16; kb++) {
        cpwait0();
        __syncthreads();
        if (kb < 15) loadW(kb + 1, (kb + 1) & 1);
        const float* wsb = Ws + (kb & 1) * 32 * 264;

#pragma unroll
        for (int ks = 0; ks < 4; ks++) {
            int kg = kb * 32 + ks * 8;
            /* A fragments (2 m-tiles), split hi/lo */
            uint32_t ahi[2][4], alo[2][4];
#pragma unroll
            for (int mt = 0; mt < 2; mt++) {
                float a0 = As[(kg + c)     * 33 + mt * 16 + g];
                float a1 = As[(kg + c)     * 33 + mt * 16 + g + 8];
                float a2 = As[(kg + c + 4) * 33 + mt * 16 + g];
                float a3 = As[(kg + c + 4) * 33 + mt * 16 + g + 8];
                ahi[mt][0] = f2tf(a0); alo[mt][0] = f2tf(a0 - __uint_as_float(ahi[mt][0]));
                ahi[mt][1] = f2tf(a1); alo[mt][1] = f2tf(a1 - __uint_as_float(ahi[mt][1]));
                ahi[mt][2] = f2tf(a2); alo[mt][2] = f2tf(a2 - __uint_as_float(ahi[mt][2]));
                ahi[mt][3] = f2tf(a3); alo[mt][3] = f2tf(a3 - __uint_as_float(ahi[mt][3]));
            }
#pragma unroll
            for (int nt = 0; nt < 4; nt++) {
                float b0 = wsb[(ks * 8 + c)     * 264 + wp * 32 + nt * 8 + g];
                float b1 = wsb[(ks * 8 + c + 4) * 264 + wp * 32 + nt * 8 + g];
                uint32_t bhi[2], blo[2];
                bhi[0] = f2tf(b0); blo[0] = f2tf(b0 - __uint_as_float(bhi[0]));
                bhi[1] = f2tf(b1); blo[1] = f2tf(b1 - __uint_as_float(bhi[1]));
#pragma unroll
                for (int mt = 0; mt < 2; mt++) {
                    mma8(acc[mt][nt], ahi[mt], bhi);
                    mma8(acc[mt][nt], ahi[mt], blo);
                    mma8(acc[mt][nt], alo[mt], bhi);
                }
            }
        }
        __syncthreads();
    }

    /* epilogue: atomic add, C fragment layout of m16n8 */
#pragma unroll
    for (int mt = 0; mt < 2; mt++)
#pragma unroll
        for (int nt = 0; nt < 4; nt++) {
            int row = mt * 16 + g;
            int col = n0 + wp * 32 + nt * 8 + 2 * c;
            atomicAdd(&C[(row)     * N + col],     acc[mt][nt][0]);
            atomicAdd(&C[(row)     * N + col + 1], acc[mt][nt][1]);
            atomicAdd(&C[(row + 8) * N + col],     acc[mt][nt][2]);
            atomicAdd(&C[(row + 8) * N + col + 1], acc[mt][nt][3]);
        }
}

/* ---------------- k/v projection: grid (2, 32), Kt = 128 ----------------- */
__global__ __launch_bounds__(256) void kvproj(
        const float* __restrict__ A, const float* __restrict__ Wk,
        const float* __restrict__ Wv) {
    __shared__ float As[32][36];
    __shared__ float Ws[32][132];
    const float* W = blockIdx.x ? Wv : Wk;
    float* C = blockIdx.x ? g_v : g_k;
    int k0 = blockIdx.y * 128;
    int t = threadIdx.x;
    int mi = t >> 5, ni = t & 31;
    float acc[4][4];
#pragma unroll
    for (int i = 0; i < 4; i++)
#pragma unroll
        for (int j = 0; j < 4; j++) acc[i][j] = 0.f;

    for (int kb = 0; kb < 128; kb += 32) {
        int kg = k0 + kb;
#pragma unroll
        for (int p = 0; p < 4; p++) {
            int i = t + p * 256;
            As[i & 31][i >> 5] = A[(i >> 5) * FF + kg + (i & 31)];
        }
#pragma unroll
        for (int p = 0; p < 4; p++) {
            int i = t + p * 256;
            int kk = i >> 5, nq = i & 31;
            *(float4*)&Ws[kk][nq * 4] = *(const float4*)&W[(kg + kk) * DD + nq * 4];
        }
        __syncthreads();
#pragma unroll
        for (int kk = 0; kk < 32; kk++) {
            float4 a = *(float4*)&As[kk][mi * 4];
            float4 w = *(float4*)&Ws[kk][ni * 4];
            acc[0][0] += a.x*w.x; acc[0][1] += a.x*w.y; acc[0][2] += a.x*w.z; acc[0][3] += a.x*w.w;
            acc[1][0] += a.y*w.x; acc[1][1] += a.y*w.y; acc[1][2] += a.y*w.z; acc[1][3] += a.y*w.w;
            acc[2][0] += a.z*w.x; acc[2][1] += a.z*w.y; acc[2][2] += a.z*w.z; acc[2][3] += a.z*w.w;
            acc[3][0] += a.w*w.x; acc[3][1] += a.w*w.y; acc[3][2] += a.w*w.z; acc[3][3] += a.w*w.w;
        }
        __syncthreads();
    }
#pragma unroll
    for (int i = 0; i < 4; i++)
#pragma unroll
        for (int j = 0; j < 4; j++)
            atomicAdd(&C[(mi * 4 + i) * DD + ni * 4 + j], acc[i][j]);
}

/* ---------------- RoPE --------------------------------------------------- */
__global__ void rope_kernel(const int* __restrict__ ci) {
    int b = blockIdx.x, hq = blockIdx.y, i = threadIdx.x;
    float pos  = (float)ci[b];
    float freq = (float)exp(-(double)i * 0.14391156831212787);
    float ang  = pos * freq;
    float s, c;
    sincosf(ang, &s, &c);
    float* p = (hq < HH) ? (g_q + (b * HH + hq) * DD) : (g_k + b * DD);
    float x1 = p[i], x2 = p[i + 64];
    p[i]      = x1 * c - x2 * s;
    p[i + 64] = x2 * c + x1 * s;
}

/* ---------------- flash-decode attention (unchanged from R1) ------------- */
__global__ __launch_bounds__(256) void attn_kernel(
        const float* __restrict__ Kc, const float* __restrict__ Vc,
        const int* __restrict__ ci) {
    extern __shared__ float sm[];
    float* qs = sm;
    float* ks = sm + 4608;
    float* vs = ks + 16384;
    float* ps = vs + 16384;
    const float4* qs4 = (const float4*)qs;
    const float4* ks4 = (const float4*)ks;
    float4* vs4 = (float4*)vs;
    float4* ps4 = (float4*)ps;
    uint32_t ks_u = s2u(ks);

    int b = blockIdx.x, sp = blockIdx.y;
    int idx = ci[b];
    int c0  = sp * CH;
    int t = threadIdx.x, w = t >> 5, lane = t & 31;

    int ntiles = 0;
    if (c0 <= idx) ntiles = (min(idx + 1 - c0, CH) + TL - 1) >> 7;

    const float* Kb = Kc + (size_t)b * DD * LL;
    const float* Vb = Vc + (size_t)b * DD * LL;

    if (ntiles > 0) {
#pragma unroll
        for (int p = 0; p < 16; p++) {
            int c = t + p * 256;
            int d = c >> 5, u = c & 31;
            cpa16(ks_u + (uint32_t)(d * 512 + u * 16),
                  Kb + (size_t)d * LL + c0 + 4 * u);
        }
        cpcommit();
    }

#pragma unroll
    for (int p = 0; p < 16; p++) {
        int i = t + p * 256;
        int h = i >> 7, d = i & 127;
        qs[d * 36 + h] = g_q[b * HH * DD + i] * SCALE;
    }

    float4 o0 = {0,0,0,0}, o1 = {0,0,0,0}, o2 = {0,0,0,0}, o3 = {0,0,0,0};
    float m_r[4] = {-1e30f,-1e30f,-1e30f,-1e30f};
    float s_r[4] = {0,0,0,0};

    __syncthreads();

    for (int it = 0; it < ntiles; it++) {
        int l0 = c0 + it * TL;
        int hot = (l0 <= idx) && (idx < l0 + TL);

        float4 vr[16];
#pragma unroll
        for (int s = 0; s < 4; s++) {
            int dB = w + 8 * s;
#pragma unroll
            for (int j = 0; j < 4; j++)
                vr[s * 4 + j] = *(const float4*)&Vb[(size_t)(4 * dB + j) * LL + l0 + 4 * lane];
        }

        cpwait0();
        __syncthreads();
        if (hot) {
            if (t < 128) ks[t * 128 + (idx - l0)] += g_k[b * DD + t];
            __syncthreads();
        }

        float4 f0 = {0,0,0,0}, f1 = {0,0,0,0}, f2 = {0,0,0,0}, f3 = {0,0,0,0};
#pragma unroll 4
        for (int d = 0; d < 128; d++) {
            float4 q4 = qs4[d * 9 + w];
            float4 k4 = ks4[d * 32 + lane];
            f0.x += q4.x*k4.x; f0.y += q4.x*k4.y; f0.z += q4.x*k4.z; f0.w += q4.x*k4.w;
            f1.x += q4.y*k4.x; f1.y += q4.y*k4.y; f1.z += q4.y*k4.z; f1.w += q4.y*k4.w;
            f2.x += q4.z*k4.x; f2.y += q4.z*k4.y; f2.z += q4.z*k4.z; f2.w += q4.z*k4.w;
            f3.x += q4.w*k4.x; f3.y += q4.w*k4.y; f3.z += q4.w*k4.z; f3.w += q4.w*k4.w;
        }
        __syncthreads();

        if (it + 1 < ntiles) {
            int l0n = l0 + TL;
#pragma unroll
            for (int p = 0; p < 16; p++) {
                int c = t + p * 256;
                int d = c >> 5, u = c & 31;
                cpa16(ks_u + (uint32_t)(d * 512 + u * 16),
                      Kb + (size_t)d * LL + l0n + 4 * u);
            }
            cpcommit();
        }

        if (l0 + TL - 1 > idx) {
            int lb = l0 + 4 * lane;
            if (lb + 0 > idx) { f0.x = -1e30f; f1.x = -1e30f; f2.x = -1e30f; f3.x = -1e30f; }
            if (lb + 1 > idx) { f0.y = -1e30f; f1.y = -1e30f; f2.y = -1e30f; f3.y = -1e30f; }
            if (lb + 2 > idx) { f0.z = -1e30f; f1.z = -1e30f; f2.z = -1e30f; f3.z = -1e30f; }
            if (lb + 3 > idx) { f0.w = -1e30f; f1.w = -1e30f; f2.w = -1e30f; f3.w = -1e30f; }
        }

        float corr[4];
#pragma unroll
        for (int hj = 0; hj < 4; hj++) {
            float4 f = (hj == 0) ? f0 : (hj == 1) ? f1 : (hj == 2) ? f2 : f3;
            float tm = fmaxf(fmaxf(f.x, f.y), fmaxf(f.z, f.w));
            tm = fmaxf(tm, __shfl_xor_sync(0xffffffffu, tm, 16));
            tm = fmaxf(tm, __shfl_xor_sync(0xffffffffu, tm, 8));
            tm = fmaxf(tm, __shfl_xor_sync(0xffffffffu, tm, 4));
            tm = fmaxf(tm, __shfl_xor_sync(0xffffffffu, tm, 2));
            tm = fmaxf(tm, __shfl_xor_sync(0xffffffffu, tm, 1));
            float mn = fmaxf(m_r[hj], tm);
            corr[hj] = __expf(m_r[hj] - mn);
            float p0 = __expf(f.x - mn), p1 = __expf(f.y - mn);
            float p2 = __expf(f.z - mn), p3 = __expf(f.w - mn);
            float ls = p0 + p1 + p2 + p3;
            ls += __shfl_xor_sync(0xffffffffu, ls, 16);
            ls += __shfl_xor_sync(0xffffffffu, ls, 8);
            ls += __shfl_xor_sync(0xffffffffu, ls, 4);
            ls += __shfl_xor_sync(0xffffffffu, ls, 2);
            ls += __shfl_xor_sync(0xffffffffu, ls, 1);
            s_r[hj] = s_r[hj] * corr[hj] + ls;
            m_r[hj] = mn;
            ps4[(4 * w + hj) * 32 + lane] = make_float4(p0, p1, p2, p3);
        }
        o0.x *= corr[0]; o0.y *= corr[0]; o0.z *= corr[0]; o0.w *= corr[0];
        o1.x *= corr[1]; o1.y *= corr[1]; o1.z *= corr[1]; o1.w *= corr[1];
        o2.x *= corr[2]; o2.y *= corr[2]; o2.z *= corr[2]; o2.w *= corr[2];
        o3.x *= corr[3]; o3.y *= corr[3]; o3.z *= corr[3]; o3.w *= corr[3];

#pragma unroll
        for (int s = 0; s < 4; s++) {
            int dB = w + 8 * s;
            int un = dB ^ (lane & 7);
            float4 a = vr[s*4+0], bb = vr[s*4+1], cc = vr[s*4+2], dd = vr[s*4+3];
            vs4[(4*lane + 0) * 32 + un] = make_float4(a.x, bb.x, cc.x, dd.x);
            vs4[(4*lane + 1) * 32 + un] = make_float4(a.y, bb.y, cc.y, dd.y);
            vs4[(4*lane + 2) * 32 + un] = make_float4(a.z, bb.z, cc.z, dd.z);
            vs4[(4*lane + 3) * 32 + un] = make_float4(a.w, bb.w, cc.w, dd.w);
        }
        __syncthreads();
        if (hot) {
            if (t < 128) {
                int li = idx - l0;
                int sw = (li >> 2) & 7;
                vs[li * 128 + (((t >> 2) ^ sw) << 2) + (t & 3)] += g_v[b * DD + t];
            }
            __syncthreads();
        }

#pragma unroll 2
        for (int lt = 0; lt < 128; lt += 4) {
            int swl = (lt >> 2) & 7;
            int vu = lane ^ swl;
            float4 v0 = vs4[(lt + 0) * 32 + vu];
            float4 v1 = vs4[(lt + 1) * 32 + vu];
            float4 v2 = vs4[(lt + 2) * 32 + vu];
            float4 v3 = vs4[(lt + 3) * 32 + vu];
            float4 pA = ps4[(4 * w + 0) * 32 + (lt >> 2)];
            float4 pB = ps4[(4 * w + 1) * 32 + (lt >> 2)];
            float4 pC = ps4[(4 * w + 2) * 32 + (lt >> 2)];
            float4 pD = ps4[(4 * w + 3) * 32 + (lt >> 2)];
            o0.x += pA.x*v0.x + pA.y*v1.x + pA.z*v2.x + pA.w*v3.x;
            o0.y += pA.x*v0.y + pA.y*v1.y + pA.z*v2.y + pA.w*v3.y;
            o0.z += pA.x*v0.z + pA.y*v1.z + pA.z*v2.z + pA.w*v3.z;
            o0.w += pA.x*v0.w + pA.y*v1.w + pA.z*v2.w + pA.w*v3.w;
            o1.x += pB.x*v0.x + pB.y*v1.x + pB.z*v2.x + pB.w*v3.x;
            o1.y += pB.x*v0.y + pB.y*v1.y + pB.z*v2.y + pB.w*v3.y;
            o1.z += pB.x*v0.z + pB.y*v1.z + pB.z*v2.z + pB.w*v3.z;
            o1.w += pB.x*v0.w + pB.y*v1.w + pB.z*v2.w + pB.w*v3.w;
            o2.x += pC.x*v0.x + pC.y*v1.x + pC.z*v2.x + pC.w*v3.x;
            o2.y += pC.x*v0.y + pC.y*v1.y + pC.z*v2.y + pC.w*v3.y;
            o2.z += pC.x*v0.z + pC.y*v1.z + pC.z*v2.z + pC.w*v3.z;
            o2.w += pC.x*v0.w + pC.y*v1.w + pC.z*v2.w + pC.w*v3.w;
            o3.x += pD.x*v0.x + pD.y*v1.x + pD.z*v2.x + pD.w*v3.x;
            o3.y += pD.x*v0.y + pD.y*v1.y + pD.z*v2.y + pD.w*v3.y;
            o3.z += pD.x*v0.z + pD.y*v1.z + pD.z*v2.z + pD.w*v3.z;
            o3.w += pD.x*v0.w + pD.y*v1.w + pD.z*v2.w + pD.w*v3.w;
        }
        __syncthreads();
    }

    int pb = (b * NSPLIT + sp) * HH;
    if (lane == 0) {
#pragma unroll
        for (int hj = 0; hj < 4; hj++) {
            g_pm[pb + 4 * w + hj]   = m_r[hj];
            g_psum[pb + 4 * w + hj] = s_r[hj];
        }
    }
    *(float4*)&g_po[((size_t)pb + 4 * w + 0) * DD + 4 * lane] = o0;
    *(float4*)&g_po[((size_t)pb + 4 * w + 1) * DD + 4 * lane] = o1;
    *(float4*)&g_po[((size_t)pb + 4 * w + 2) * DD + 4 * lane] = o2;
    *(float4*)&g_po[((size_t)pb + 4 * w + 3) * DD + 4 * lane] = o3;
}

/* ---------------- combine ------------------------------------------------ */
__global__ void combine_kernel() {
    int bh = blockIdx.x;
    int b = bh >> 5, h = bh & 31;
    int d = threadIdx.x;
    float m = -1e30f;
#pragma unroll
    for (int s = 0; s < NSPLIT; s++)
        m = fmaxf(m, g_pm[(b * NSPLIT + s) * HH + h]);
    float S = 0.f, acc = 0.f;
#pragma unroll
    for (int s = 0; s < NSPLIT; s++) {
        int ib = (b * NSPLIT + s) * HH + h;
        float w = __expf(g_pm[ib] - m);
        S   += w * g_psum[ib];
        acc += w * g_po[(size_t)ib * DD + d];
    }
    g_attn[(b * HH + h) * DD + d] = acc / S;
}

/* ---------------- launch ------------------------------------------------- */
extern "C" void kernel_launch(void* const* d_in, const int* in_sizes, int n_in,
                              void* d_out, int out_size) {
    const float* x  = (const float*)d_in[0];
    const float* Kc = (const float*)d_in[1];
    const float* Vc = (const float*)d_in[2];
    const float* Wq = (const float*)d_in[3];
    const float* Wk = (const float*)d_in[4];
    const float* Wv = (const float*)d_in[5];
    const float* Wo = (const float*)d_in[6];
    const int*   ci = (const int*)d_in[7];
    float* out = (float*)d_out;

    float *qp, *ap;
    cudaGetSymbolAddress((void**)&qp, g_q);
    cudaGetSymbolAddress((void**)&ap, g_attn);

    cudaFuncSetAttribute(tgemm32,
                         cudaFuncAttributeMaxDynamicSharedMemorySize, 135168);
    cudaFuncSetAttribute(attn_kernel,
                         cudaFuncAttributeMaxDynamicSharedMemorySize, 165888);

    zero_kernel<<<512, 256>>>(out);
    tgemm32<<<dim3(16, SPLITK), 256, 135168>>>(x, Wq, qp, 4096);
    kvproj<<<dim3(2, 32), 256>>>(x, Wk, Wv);
    rope_kernel<<<dim3(32, 33), 64>>>(ci);
    attn_kernel<<<dim3(32, NSPLIT), 256, 165888>>>(Kc, Vc, ci);
    combine_kernel<<<1024, 128>>>();
    tgemm32<<<dim3(16, SPLITK), 256, 135168>>>(ap, Wo, out, 4096);
}

// round 4
// speedup vs baseline: 4.4202x; 1.1038x over previous
#include <cuda_runtime.h>
#include <math.h>
#include <stdint.h>

#define BB 32
#define FF 4096
#define HH 32
#define DD 128
#define LL 8192
#define NSPLIT 16
#define CH (LL/NSPLIT)
#define TL 128
#define LDK 132
#define SCALE 0.08838834764831845f

/* ---------------- scratch ------------------------------------------------ */
__device__ float g_q[BB*HH*DD];
__device__ float g_k[BB*DD];
__device__ float g_v[BB*DD];
__device__ float g_attn[BB*HH*DD];
__device__ float g_pm[BB*NSPLIT*HH];
__device__ float g_psum[BB*NSPLIT*HH];
__device__ float g_po[BB*NSPLIT*HH*DD];
__device__ float g_freq[64];

/* ---------------- helpers ------------------------------------------------ */
__device__ __forceinline__ uint32_t s2u(const void* p) {
    return (uint32_t)__cvta_generic_to_shared(p);
}
__device__ __forceinline__ void cpa16(uint32_t s, const void* g) {
    asm volatile("cp.async.cg.shared.global [%0], [%1], 16;" :: "r"(s), "l"(g));
}
__device__ __forceinline__ void cpcommit() { asm volatile("cp.async.commit_group;"); }
__device__ __forceinline__ void cpwait0()  { asm volatile("cp.async.wait_group 0;"); }

__device__ __forceinline__ uint32_t f2tf(float x) {
    uint32_t r; asm("cvt.rna.tf32.f32 %0, %1;" : "=r"(r) : "f"(x)); return r;
}
__device__ __forceinline__ void mma8(float* d, const uint32_t* a, const uint32_t* b) {
    asm volatile("mma.sync.aligned.m16n8k8.row.col.f32.tf32.tf32.f32 "
        "{%0,%1,%2,%3},{%4,%5,%6,%7},{%8,%9},{%0,%1,%2,%3};"
        : "+f"(d[0]), "+f"(d[1]), "+f"(d[2]), "+f"(d[3])
        : "r"(a[0]), "r"(a[1]), "r"(a[2]), "r"(a[3]), "r"(b[0]), "r"(b[1]));
}

/* ---------------- zero + freq table -------------------------------------- */
__global__ void zero_kernel(float* __restrict__ out) {
    int i = blockIdx.x * 256 + threadIdx.x;
    g_q[i] = 0.f;
    out[i] = 0.f;
    if (i < BB*DD) { g_k[i] = 0.f; g_v[i] = 0.f; }
    if (i < 64) g_freq[i] = (float)exp(-(double)i * 0.14391156831212787);
}

/* ---------------- tensor GEMM (3xTF32): C[32,N] += A[32,4096]*W[4096,N] -- */
#define SPLITK 8
#define KSL (FF/SPLITK)
__global__ __launch_bounds__(256) void tgemm32(
        const float* __restrict__ A, const float* __restrict__ W,
        float* __restrict__ C, int N) {
    extern __shared__ float sm[];
    float* As = sm;
    float* Ws = sm + 16896;
    uint32_t ws_u = s2u(Ws);

    int n0 = blockIdx.x * 256;
    int k0 = blockIdx.y * KSL;
    int t = threadIdx.x, wp = t >> 5, lane = t & 31;
    int g = lane >> 2, c = lane & 3;

#pragma unroll
    for (int p = 0; p < 64; p++) {
        int i = t + p * 256;
        int m = i >> 9, k = i & 511;
        As[k * 33 + m] = A[m * FF + k0 + k];
    }
    auto loadW = [&](int kb, int buf) {
        const float* src = W + (size_t)(k0 + kb * 32) * N + n0;
#pragma unroll
        for (int p = 0; p < 8; p++) {
            int ci = t + p * 256;
            int kk = ci >> 6, u = ci & 63;
            cpa16(ws_u + (uint32_t)((buf * 32 + kk) * 264 + 4 * u) * 4,
                  src + (size_t)kk * N + 4 * u);
        }
        cpcommit();
    };
    loadW(0, 0);

    float acc[2][4][4];
#pragma unroll
    for (int mt = 0; mt < 2; mt++)
#pragma unroll
        for (int nt = 0; nt < 4; nt++)
#pragma unroll
            for (int r = 0; r < 4; r++) acc[mt][nt][r] = 0.f;

    for (int kb = 0; kb < 16; kb++) {
        cpwait0();
        __syncthreads();
        if (kb < 15) loadW(kb + 1, (kb + 1) & 1);
        const float* wsb = Ws + (kb & 1) * 32 * 264;

#pragma unroll
        for (int ks = 0; ks < 4; ks++) {
            int kg = kb * 32 + ks * 8;
            uint32_t ahi[2][4], alo[2][4];
#pragma unroll
            for (int mt = 0; mt < 2; mt++) {
                float a0 = As[(kg + c)     * 33 + mt * 16 + g];
                float a1 = As[(kg + c)     * 33 + mt * 16 + g + 8];
                float a2 = As[(kg + c + 4) * 33 + mt * 16 + g];
                float a3 = As[(kg + c + 4) * 33 + mt * 16 + g + 8];
                ahi[mt][0] = f2tf(a0); alo[mt][0] = f2tf(a0 - __uint_as_float(ahi[mt][0]));
                ahi[mt][1] = f2tf(a1); alo[mt][1] = f2tf(a1 - __uint_as_float(ahi[mt][1]));
                ahi[mt][2] = f2tf(a2); alo[mt][2] = f2tf(a2 - __uint_as_float(ahi[mt][2]));
                ahi[mt][3] = f2tf(a3); alo[mt][3] = f2tf(a3 - __uint_as_float(ahi[mt][3]));
            }
#pragma unroll
            for (int nt = 0; nt < 4; nt++) {
                float b0 = wsb[(ks * 8 + c)     * 264 + wp * 32 + nt * 8 + g];
                float b1 = wsb[(ks * 8 + c + 4) * 264 + wp * 32 + nt * 8 + g];
                uint32_t bhi[2], blo[2];
                bhi[0] = f2tf(b0); blo[0] = f2tf(b0 - __uint_as_float(bhi[0]));
                bhi[1] = f2tf(b1); blo[1] = f2tf(b1 - __uint_as_float(bhi[1]));
#pragma unroll
                for (int mt = 0; mt < 2; mt++) {
                    mma8(acc[mt][nt], ahi[mt], bhi);
                    mma8(acc[mt][nt], ahi[mt], blo);
                    mma8(acc[mt][nt], alo[mt], bhi);
                }
            }
        }
        __syncthreads();
    }
#pragma unroll
    for (int mt = 0; mt < 2; mt++)
#pragma unroll
        for (int nt = 0; nt < 4; nt++) {
            int row = mt * 16 + g;
            int col = n0 + wp * 32 + nt * 8 + 2 * c;
            atomicAdd(&C[(row)     * N + col],     acc[mt][nt][0]);
            atomicAdd(&C[(row)     * N + col + 1], acc[mt][nt][1]);
            atomicAdd(&C[(row + 8) * N + col],     acc[mt][nt][2]);
            atomicAdd(&C[(row + 8) * N + col + 1], acc[mt][nt][3]);
        }
}

/* ---------------- k/v projection ----------------------------------------- */
__global__ __launch_bounds__(256) void kvproj(
        const float* __restrict__ A, const float* __restrict__ Wk,
        const float* __restrict__ Wv) {
    __shared__ float As[32][36];
    __shared__ float Ws[32][132];
    const float* W = blockIdx.x ? Wv : Wk;
    float* C = blockIdx.x ? g_v : g_k;
    int k0 = blockIdx.y * 128;
    int t = threadIdx.x;
    int mi = t >> 5, ni = t & 31;
    float acc[4][4];
#pragma unroll
    for (int i = 0; i < 4; i++)
#pragma unroll
        for (int j = 0; j < 4; j++) acc[i][j] = 0.f;

    for (int kb = 0; kb < 128; kb += 32) {
        int kg = k0 + kb;
#pragma unroll
        for (int p = 0; p < 4; p++) {
            int i = t + p * 256;
            As[i & 31][i >> 5] = A[(i >> 5) * FF + kg + (i & 31)];
        }
#pragma unroll
        for (int p = 0; p < 4; p++) {
            int i = t + p * 256;
            int kk = i >> 5, nq = i & 31;
            *(float4*)&Ws[kk][nq * 4] = *(const float4*)&W[(kg + kk) * DD + nq * 4];
        }
        __syncthreads();
#pragma unroll
        for (int kk = 0; kk < 32; kk++) {
            float4 a = *(float4*)&As[kk][mi * 4];
            float4 w = *(float4*)&Ws[kk][ni * 4];
            acc[0][0] += a.x*w.x; acc[0][1] += a.x*w.y; acc[0][2] += a.x*w.z; acc[0][3] += a.x*w.w;
            acc[1][0] += a.y*w.x; acc[1][1] += a.y*w.y; acc[1][2] += a.y*w.z; acc[1][3] += a.y*w.w;
            acc[2][0] += a.z*w.x; acc[2][1] += a.z*w.y; acc[2][2] += a.z*w.z; acc[2][3] += a.z*w.w;
            acc[3][0] += a.w*w.x; acc[3][1] += a.w*w.y; acc[3][2] += a.w*w.z; acc[3][3] += a.w*w.w;
        }
        __syncthreads();
    }
#pragma unroll
    for (int i = 0; i < 4; i++)
#pragma unroll
        for (int j = 0; j < 4; j++)
            atomicAdd(&C[(mi * 4 + i) * DD + ni * 4 + j], acc[i][j]);
}

/* ---------------- RoPE (table-based) ------------------------------------- */
__global__ void rope_kernel(const int* __restrict__ ci) {
    int b = blockIdx.x, hq = blockIdx.y, i = threadIdx.x;
    float pos  = (float)ci[b];
    float ang  = pos * g_freq[i];
    float s, c;
    sincosf(ang, &s, &c);
    float* p = (hq < HH) ? (g_q + (b * HH + hq) * DD) : (g_k + b * DD);
    float x1 = p[i], x2 = p[i + 64];
    p[i]      = x1 * c - x2 * s;
    p[i + 64] = x2 * c + x1 * s;
}

/* ---------------- flash-decode attention (tensor cores) -------------------
 * grid (B, NSPLIT), 256 thr = 8 warps.
 * QK: A=q[h][d], B=K[d][l] (native).  PV: A=p[h][l], B=V[l][d] (native).
 * warp w covers l-range / d-range [16w, 16w+16).
 * smem floats: qhi 4224 | qlo 4224 | psh 4224 | psl 4224 | scorr 32 |
 *              ks 16896 | vs 16896  -> 202880 B                           */
__global__ __launch_bounds__(256) void attn_kernel(
        const float* __restrict__ Kc, const float* __restrict__ Vc,
        const int* __restrict__ ci) {
    extern __shared__ float sm[];
    float* qhi = sm;
    float* qlo = sm + 4224;
    float* psh = sm + 8448;
    float* psl = sm + 12672;
    float* scr = sm + 16896;
    float* ks  = sm + 16928;
    float* vs  = sm + 33824;
    uint32_t ks_u = s2u(ks), vs_u = s2u(vs);

    int b = blockIdx.x, sp = blockIdx.y;
    int idx = ci[b];
    int c0  = sp * CH;
    int t = threadIdx.x, w = t >> 5, lane = t & 31;
    int g = lane >> 2, c = lane & 3;

    int ntiles = 0;
    if (c0 <= idx) ntiles = (min(idx + 1 - c0, CH) + TL - 1) >> 7;

    const float* Kb = Kc + (size_t)b * DD * LL;
    const float* Vb = Vc + (size_t)b * DD * LL;

    if (ntiles > 0) {
#pragma unroll
        for (int p = 0; p < 16; p++) {
            int i = t + p * 256; int d = i >> 5, u = i & 31;
            cpa16(ks_u + (uint32_t)(d * LDK + 4 * u) * 4, Kb + (size_t)d * LL + c0 + 4 * u);
        }
        cpcommit();
#pragma unroll
        for (int p = 0; p < 16; p++) {
            int i = t + p * 256; int d = i >> 5, u = i & 31;
            cpa16(vs_u + (uint32_t)(d * LDK + 4 * u) * 4, Vb + (size_t)d * LL + c0 + 4 * u);
        }
        cpcommit();
    }

    /* q -> split tf32 hi/lo, pre-scaled */
#pragma unroll
    for (int p = 0; p < 16; p++) {
        int i = t + p * 256; int h = i >> 7, d = i & 127;
        float v = g_q[b * HH * DD + i] * SCALE;
        uint32_t hi = f2tf(v);
        qhi[h * LDK + d] = __uint_as_float(hi);
        qlo[h * LDK + d] = __uint_as_float(f2tf(v - __uint_as_float(hi)));
    }

    float acco[2][2][4];
#pragma unroll
    for (int mt = 0; mt < 2; mt++)
#pragma unroll
        for (int nt = 0; nt < 2; nt++)
#pragma unroll
            for (int r = 0; r < 4; r++) acco[mt][nt][r] = 0.f;
    float m_r[4] = {-1e30f, -1e30f, -1e30f, -1e30f};
    float s_r[4] = {0.f, 0.f, 0.f, 0.f};

    __syncthreads();

    for (int it = 0; it < ntiles; it++) {
        int l0 = c0 + it * TL;
        int hot = (l0 <= idx) && (idx < l0 + TL);
        cpwait0();
        __syncthreads();
        if (hot) {
            if (t < 128) {
                int li = idx - l0;
                ks[t * LDK + li] += g_k[b * DD + t];
                vs[t * LDK + li] += g_v[b * DD + t];
            }
            __syncthreads();
        }

        /* ---- QK ---- */
        float accq[2][2][4];
#pragma unroll
        for (int mt = 0; mt < 2; mt++)
#pragma unroll
            for (int nt = 0; nt < 2; nt++)
#pragma unroll
                for (int r = 0; r < 4; r++) accq[mt][nt][r] = 0.f;

#pragma unroll 4
        for (int kd = 0; kd < 16; kd++) {
            int d0 = kd * 8;
            uint32_t ah[2][4], al[2][4];
#pragma unroll
            for (int mt = 0; mt < 2; mt++) {
                int r0 = (mt * 16 + g) * LDK, r1 = (mt * 16 + g + 8) * LDK;
                ah[mt][0] = __float_as_uint(qhi[r0 + d0 + c]);
                ah[mt][1] = __float_as_uint(qhi[r1 + d0 + c]);
                ah[mt][2] = __float_as_uint(qhi[r0 + d0 + c + 4]);
                ah[mt][3] = __float_as_uint(qhi[r1 + d0 + c + 4]);
                al[mt][0] = __float_as_uint(qlo[r0 + d0 + c]);
                al[mt][1] = __float_as_uint(qlo[r1 + d0 + c]);
                al[mt][2] = __float_as_uint(qlo[r0 + d0 + c + 4]);
                al[mt][3] = __float_as_uint(qlo[r1 + d0 + c + 4]);
            }
#pragma unroll
            for (int nt = 0; nt < 2; nt++) {
                int nb = w * 16 + nt * 8 + g;
                float b0 = ks[(d0 + c) * LDK + nb];
                float b1 = ks[(d0 + c + 4) * LDK + nb];
                uint32_t bh[2], bl[2];
                bh[0] = f2tf(b0); bl[0] = f2tf(b0 - __uint_as_float(bh[0]));
                bh[1] = f2tf(b1); bl[1] = f2tf(b1 - __uint_as_float(bh[1]));
#pragma unroll
                for (int mt = 0; mt < 2; mt++) {
                    mma8(accq[mt][nt], ah[mt], bh);
                    mma8(accq[mt][nt], al[mt], bh);
                    mma8(accq[mt][nt], ah[mt], bl);
                }
            }
        }
        /* logits -> psh */
#pragma unroll
        for (int mt = 0; mt < 2; mt++)
#pragma unroll
            for (int nt = 0; nt < 2; nt++) {
                int r0 = mt * 16 + g, cb = w * 16 + nt * 8 + 2 * c;
                psh[r0 * LDK + cb]           = accq[mt][nt][0];
                psh[r0 * LDK + cb + 1]       = accq[mt][nt][1];
                psh[(r0 + 8) * LDK + cb]     = accq[mt][nt][2];
                psh[(r0 + 8) * LDK + cb + 1] = accq[mt][nt][3];
            }
        __syncthreads();

        /* prefetch next K (ks free) */
        if (it + 1 < ntiles) {
            int l0n = l0 + TL;
#pragma unroll
            for (int p = 0; p < 16; p++) {
                int i = t + p * 256; int d = i >> 5, u = i & 31;
                cpa16(ks_u + (uint32_t)(d * LDK + 4 * u) * 4, Kb + (size_t)d * LL + l0n + 4 * u);
            }
            cpcommit();
        }

        /* ---- softmax: warp w owns heads 4w..4w+3, lane covers l=4*lane ---- */
#pragma unroll
        for (int hj = 0; hj < 4; hj++) {
            int h = 4 * w + hj;
            float4 f = *(float4*)&psh[h * LDK + 4 * lane];
            if (l0 + TL - 1 > idx) {
                int lb = l0 + 4 * lane;
                if (lb     > idx) f.x = -1e30f;
                if (lb + 1 > idx) f.y = -1e30f;
                if (lb + 2 > idx) f.z = -1e30f;
                if (lb + 3 > idx) f.w = -1e30f;
            }
            float tm = fmaxf(fmaxf(f.x, f.y), fmaxf(f.z, f.w));
            tm = fmaxf(tm, __shfl_xor_sync(0xffffffffu, tm, 16));
            tm = fmaxf(tm, __shfl_xor_sync(0xffffffffu, tm, 8));
            tm = fmaxf(tm, __shfl_xor_sync(0xffffffffu, tm, 4));
            tm = fmaxf(tm, __shfl_xor_sync(0xffffffffu, tm, 2));
            tm = fmaxf(tm, __shfl_xor_sync(0xffffffffu, tm, 1));
            float mn = fmaxf(m_r[hj], tm);
            float co = __expf(m_r[hj] - mn);
            float p0 = __expf(f.x - mn), p1 = __expf(f.y - mn);
            float p2 = __expf(f.z - mn), p3 = __expf(f.w - mn);
            float ls = p0 + p1 + p2 + p3;
            ls += __shfl_xor_sync(0xffffffffu, ls, 16);
            ls += __shfl_xor_sync(0xffffffffu, ls, 8);
            ls += __shfl_xor_sync(0xffffffffu, ls, 4);
            ls += __shfl_xor_sync(0xffffffffu, ls, 2);
            ls += __shfl_xor_sync(0xffffffffu, ls, 1);
            s_r[hj] = s_r[hj] * co + ls;
            m_r[hj] = mn;
            uint32_t h0 = f2tf(p0), h1 = f2tf(p1), h2 = f2tf(p2), h3 = f2tf(p3);
            int base = h * LDK + 4 * lane;
            psh[base]     = __uint_as_float(h0);
            psh[base + 1] = __uint_as_float(h1);
            psh[base + 2] = __uint_as_float(h2);
            psh[base + 3] = __uint_as_float(h3);
            psl[base]     = __uint_as_float(f2tf(p0 - __uint_as_float(h0)));
            psl[base + 1] = __uint_as_float(f2tf(p1 - __uint_as_float(h1)));
            psl[base + 2] = __uint_as_float(f2tf(p2 - __uint_as_float(h2)));
            psl[base + 3] = __uint_as_float(f2tf(p3 - __uint_as_float(h3)));
            if (lane == 0) scr[h] = co;
        }
        __syncthreads();

        /* rescale PV accumulators */
        {
            float s0 = scr[g], s1 = scr[g + 8], s2 = scr[g + 16], s3 = scr[g + 24];
#pragma unroll
            for (int nt = 0; nt < 2; nt++) {
                acco[0][nt][0] *= s0; acco[0][nt][1] *= s0;
                acco[0][nt][2] *= s1; acco[0][nt][3] *= s1;
                acco[1][nt][0] *= s2; acco[1][nt][1] *= s2;
                acco[1][nt][2] *= s3; acco[1][nt][3] *= s3;
            }
        }

        /* ---- PV ---- */
#pragma unroll 4
        for (int kl = 0; kl < 16; kl++) {
            int k0l = kl * 8;
            uint32_t ah[2][4], al[2][4];
#pragma unroll
            for (int mt = 0; mt < 2; mt++) {
                int r0 = (mt * 16 + g) * LDK, r1 = (mt * 16 + g + 8) * LDK;
                ah[mt][0] = __float_as_uint(psh[r0 + k0l + c]);
                ah[mt][1] = __float_as_uint(psh[r1 + k0l + c]);
                ah[mt][2] = __float_as_uint(psh[r0 + k0l + c + 4]);
                ah[mt][3] = __float_as_uint(psh[r1 + k0l + c + 4]);
                al[mt][0] = __float_as_uint(psl[r0 + k0l + c]);
                al[mt][1] = __float_as_uint(psl[r1 + k0l + c]);
                al[mt][2] = __float_as_uint(psl[r0 + k0l + c + 4]);
                al[mt][3] = __float_as_uint(psl[r1 + k0l + c + 4]);
            }
#pragma unroll
            for (int nt = 0; nt < 2; nt++) {
                int nb = w * 16 + nt * 8 + g;
                float b0 = vs[nb * LDK + k0l + c];
                float b1 = vs[nb * LDK + k0l + c + 4];
                uint32_t bh[2], bl[2];
                bh[0] = f2tf(b0); bl[0] = f2tf(b0 - __uint_as_float(bh[0]));
                bh[1] = f2tf(b1); bl[1] = f2tf(b1 - __uint_as_float(bh[1]));
#pragma unroll
                for (int mt = 0; mt < 2; mt++) {
                    mma8(acco[mt][nt], ah[mt], bh);
                    mma8(acco[mt][nt], al[mt], bh);
                    mma8(acco[mt][nt], ah[mt], bl);
                }
            }
        }
        __syncthreads();

        /* prefetch next V (vs free) */
        if (it + 1 < ntiles) {
            int l0n = l0 + TL;
#pragma unroll
            for (int p = 0; p < 16; p++) {
                int i = t + p * 256; int d = i >> 5, u = i & 31;
                cpa16(vs_u + (uint32_t)(d * LDK + 4 * u) * 4, Vb + (size_t)d * LL + l0n + 4 * u);
            }
            cpcommit();
        }
    }

    /* write split partials */
    int pb = (b * NSPLIT + sp) * HH;
    if (lane == 0) {
#pragma unroll
        for (int hj = 0; hj < 4; hj++) {
            g_pm[pb + 4 * w + hj]   = m_r[hj];
            g_psum[pb + 4 * w + hj] = s_r[hj];
        }
    }
#pragma unroll
    for (int mt = 0; mt < 2; mt++)
#pragma unroll
        for (int nt = 0; nt < 2; nt++) {
            int h0 = mt * 16 + g;
            int dd = w * 16 + nt * 8 + 2 * c;
            g_po[(size_t)(pb + h0) * DD + dd]         = acco[mt][nt][0];
            g_po[(size_t)(pb + h0) * DD + dd + 1]     = acco[mt][nt][1];
            g_po[(size_t)(pb + h0 + 8) * DD + dd]     = acco[mt][nt][2];
            g_po[(size_t)(pb + h0 + 8) * DD + dd + 1] = acco[mt][nt][3];
        }
}

/* ---------------- combine ------------------------------------------------ */
__global__ void combine_kernel() {
    int bh = blockIdx.x;
    int b = bh >> 5, h = bh & 31;
    int d = threadIdx.x;
    float m = -1e30f;
#pragma unroll
    for (int s = 0; s < NSPLIT; s++)
        m = fmaxf(m, g_pm[(b * NSPLIT + s) * HH + h]);
    float S = 0.f, acc = 0.f;
#pragma unroll
    for (int s = 0; s < NSPLIT; s++) {
        int ib = (b * NSPLIT + s) * HH + h;
        float w = __expf(g_pm[ib] - m);
        S   += w * g_psum[ib];
        acc += w * g_po[(size_t)ib * DD + d];
    }
    g_attn[(b * HH + h) * DD + d] = acc / S;
}

/* ---------------- launch ------------------------------------------------- */
extern "C" void kernel_launch(void* const* d_in, const int* in_sizes, int n_in,
                              void* d_out, int out_size) {
    const float* x  = (const float*)d_in[0];
    const float* Kc = (const float*)d_in[1];
    const float* Vc = (const float*)d_in[2];
    const float* Wq = (const float*)d_in[3];
    const float* Wk = (const float*)d_in[4];
    const float* Wv = (const float*)d_in[5];
    const float* Wo = (const float*)d_in[6];
    const int*   ci = (const int*)d_in[7];
    float* out = (float*)d_out;

    float *qp, *ap;
    cudaGetSymbolAddress((void**)&qp, g_q);
    cudaGetSymbolAddress((void**)&ap, g_attn);

    cudaFuncSetAttribute(tgemm32,
                         cudaFuncAttributeMaxDynamicSharedMemorySize, 135168);
    cudaFuncSetAttribute(attn_kernel,
                         cudaFuncAttributeMaxDynamicSharedMemorySize, 202880);

    zero_kernel<<<512, 256>>>(out);
    tgemm32<<<dim3(16, SPLITK), 256, 135168>>>(x, Wq, qp, 4096);
    kvproj<<<dim3(2, 32), 256>>>(x, Wk, Wv);
    rope_kernel<<<dim3(32, 33), 64>>>(ci);
    attn_kernel<<<dim3(32, NSPLIT), 256, 202880>>>(Kc, Vc, ci);
    combine_kernel<<<1024, 128>>>();
    tgemm32<<<dim3(16, SPLITK), 256, 135168>>>(ap, Wo, out, 4096);
}